// round 11
// baseline (speedup 1.0000x reference)
#include <cuda_runtime.h>
#include <cuda_bf16.h>
#include <math.h>
#include <cstdint>

#define H       100
#define NNODES  1024    // N = B*L
#define BATCH   64
#define LSEQ    16
#define EDGES   2048
#define NNODE   40000
#define H4      25
#define NPB     2       // nodes per block in k3

// ---- int8 IMMA GEMM config ----
#define MT      128                // j rows per CTA (8 warps x m16)
#define NTILES  313                // ceil(40000/128)
#define JPAD    (NTILES * MT)      // 40064
#define KPI     128                // padded K (4 k-steps of 32)
#define KSI     4                  // k-steps
#define BRSTR   144                // smem B row stride bytes (conflict-free LDSM)
#define NTL     4                  // n8 tiles per batch: 16 P + 16 C

typedef unsigned long long ull;

#define IMMA16832(d, a, b0, b1)                                             \
    asm volatile("mma.sync.aligned.m16n8k32.row.col.s32.s8.s8.s32 "         \
        "{%0,%1,%2,%3}, {%4,%5,%6,%7}, {%8,%9}, {%0,%1,%2,%3};"             \
        : "+r"((d)[0]), "+r"((d)[1]), "+r"((d)[2]), "+r"((d)[3])            \
        : "r"((a)[0]), "r"((a)[1]), "r"((a)[2]), "r"((a)[3]),               \
          "r"(b0), "r"(b1))

#define LDSM4(r0, r1, r2, r3, addr)                                         \
    asm volatile("ldmatrix.sync.aligned.m8n8.x4.shared.b16 {%0,%1,%2,%3}, [%4];" \
        : "=r"(r0), "=r"(r1), "=r"(r2), "=r"(r3) : "r"(addr))

#define CP_ASYNC16(smaddr, gptr)                                            \
    asm volatile("cp.async.cg.shared.global [%0], [%1], 16;"                \
        :: "r"(smaddr), "l"(gptr) : "memory")
#define CP_COMMIT()  asm volatile("cp.async.commit_group;" ::: "memory")
#define CP_WAIT1()   asm volatile("cp.async.wait_group 1;" ::: "memory")
#define CP_WAIT0()   asm volatile("cp.async.wait_group 0;" ::: "memory")

static __device__ __forceinline__ uint32_t smem_u32(const void* p) {
    uint32_t a;
    asm("{ .reg .u64 t; cvta.to.shared.u64 t, %1; cvt.u32.u64 %0, t; }" : "=r"(a) : "l"(p));
    return a;
}

// ---- scratch (no allocations allowed) ----
__device__ float d_h  [NNODES * H];
__device__ float d_m  [NNODES * H];
__device__ float d_agg[NNODES * H];
__device__ float d_v  [NNODES * H];
__device__ float d_vt [NNODES * H];
__device__ float d_sh [BATCH  * H];
// int8 2-digit fixed-point operands
__device__ int8_t d_e1[(size_t)JPAD * KPI];
__device__ int8_t d_e2[(size_t)JPAD * KPI];
__device__ float  d_se[JPAD];
__device__ int8_t d_b1[BATCH * 32 * KPI];   // rows: b*32 + (n<16? vt_n : v_{n-16})
__device__ int8_t d_b2[BATCH * 32 * KPI];
__device__ float  d_sb[BATCH * 32];
__device__ int8_t d_sh1[BATCH * KPI];
__device__ int8_t d_sh2[BATCH * KPI];
__device__ float  d_ssh[BATCH];

// ------------------------------------------------------------------
// K1: h = embed[x];  m = h @ ggc_w[0];  agg = 0
// ------------------------------------------------------------------
__global__ void k1_gather_m(const int* __restrict__ x,
                            const float* __restrict__ embed,
                            const float* __restrict__ ggc)
{
    int i = blockIdx.x;
    int t = threadIdx.x;
    __shared__ float hs[H];
    int xi = x[i];
    if (t < H) {
        float val = embed[(size_t)xi * H + t];
        hs[t] = val;
        d_h[i * H + t] = val;
    }
    __syncthreads();
    if (t < H) {
        float acc = 0.f;
        #pragma unroll 4
        for (int k = 0; k < H; k++)
            acc = fmaf(hs[k], ggc[k * H + t], acc);
        d_m[i * H + t]   = acc;
        d_agg[i * H + t] = 0.f;
    }
}

// ------------------------------------------------------------------
// K2: agg[dst] += w_e * m[src]
// ------------------------------------------------------------------
__global__ void k2_scatter(const int* __restrict__ ei,
                           const float* __restrict__ ew)
{
    int idx = blockIdx.x * blockDim.x + threadIdx.x;
    if (idx >= EDGES * H) return;
    int e = idx / H;
    int h = idx - e * H;
    int src = ei[e];
    int dst = ei[EDGES + e];
    atomicAdd(&d_agg[dst * H + h], ew[e] * d_m[src * H + h]);
}

// ------------------------------------------------------------------
// K3: GRU + fused W2-pre/vt. NPB=2 -> 512 CTAs; unrolled k-loops for MLP.
// ------------------------------------------------------------------
__global__ void __launch_bounds__(128)
k3_gru_post(const float* __restrict__ wih,
            const float* __restrict__ whh,
            const float* __restrict__ bih,
            const float* __restrict__ bhh,
            const float* __restrict__ W2,
            const float* __restrict__ b2,
            const float* __restrict__ Wt,
            const float* __restrict__ bt)
{
    int node0 = blockIdx.x * NPB;
    int c = threadIdx.x;
    __shared__ __align__(16) float ag[NPB * H];
    __shared__ __align__(16) float hh[NPB * H];
    __shared__ __align__(16) float vv[NPB * H];

    for (int idx = c; idx < NPB * H; idx += 128) {
        ag[idx] = d_agg[node0 * H + idx];
        hh[idx] = d_h  [node0 * H + idx];
    }
    __syncthreads();

    if (c < H) {
        float air[NPB], aiz[NPB], ain[NPB], ahr[NPB], ahz[NPB], ahn[NPB];
        float br = bih[c], bz = bih[H + c], bn = bih[2 * H + c];
        float cr = bhh[c], cz = bhh[H + c], cn = bhh[2 * H + c];
        #pragma unroll
        for (int n = 0; n < NPB; n++) {
            air[n] = br; aiz[n] = bz; ain[n] = bn;
            ahr[n] = cr; ahz[n] = cz; ahn[n] = cn;
        }
        const float4* wr4 = (const float4*)(wih + (size_t)c * H);
        const float4* wz4 = (const float4*)(wih + (size_t)(H + c) * H);
        const float4* wn4 = (const float4*)(wih + (size_t)(2 * H + c) * H);
        const float4* ur4 = (const float4*)(whh + (size_t)c * H);
        const float4* uz4 = (const float4*)(whh + (size_t)(H + c) * H);
        const float4* un4 = (const float4*)(whh + (size_t)(2 * H + c) * H);

        #pragma unroll 5
        for (int k = 0; k < H4; k++) {
            float4 wr = wr4[k], wz = wz4[k], wn = wn4[k];
            float4 ur = ur4[k], uz = uz4[k], un = un4[k];
            #pragma unroll
            for (int n = 0; n < NPB; n++) {
                float4 a  = *(const float4*)&ag[n * H + 4 * k];
                float4 hv = *(const float4*)&hh[n * H + 4 * k];
                air[n] = fmaf(a.x, wr.x, air[n]); air[n] = fmaf(a.y, wr.y, air[n]);
                air[n] = fmaf(a.z, wr.z, air[n]); air[n] = fmaf(a.w, wr.w, air[n]);
                aiz[n] = fmaf(a.x, wz.x, aiz[n]); aiz[n] = fmaf(a.y, wz.y, aiz[n]);
                aiz[n] = fmaf(a.z, wz.z, aiz[n]); aiz[n] = fmaf(a.w, wz.w, aiz[n]);
                ain[n] = fmaf(a.x, wn.x, ain[n]); ain[n] = fmaf(a.y, wn.y, ain[n]);
                ain[n] = fmaf(a.z, wn.z, ain[n]); ain[n] = fmaf(a.w, wn.w, ain[n]);
                ahr[n] = fmaf(hv.x, ur.x, ahr[n]); ahr[n] = fmaf(hv.y, ur.y, ahr[n]);
                ahr[n] = fmaf(hv.z, ur.z, ahr[n]); ahr[n] = fmaf(hv.w, ur.w, ahr[n]);
                ahz[n] = fmaf(hv.x, uz.x, ahz[n]); ahz[n] = fmaf(hv.y, uz.y, ahz[n]);
                ahz[n] = fmaf(hv.z, uz.z, ahz[n]); ahz[n] = fmaf(hv.w, uz.w, ahz[n]);
                ahn[n] = fmaf(hv.x, un.x, ahn[n]); ahn[n] = fmaf(hv.y, un.y, ahn[n]);
                ahn[n] = fmaf(hv.z, un.z, ahn[n]); ahn[n] = fmaf(hv.w, un.w, ahn[n]);
            }
        }
        #pragma unroll
        for (int n = 0; n < NPB; n++) {
            float r  = 1.f / (1.f + __expf(-(air[n] + ahr[n])));
            float zg = 1.f / (1.f + __expf(-(aiz[n] + ahz[n])));
            float ng = tanhf(ain[n] + r * ahn[n]);
            float nv = (1.f - zg) * ng + zg * hh[n * H + c];
            vv[n * H + c] = nv;
            d_v[(node0 + n) * H + c] = nv;
        }
    }
    __syncthreads();

    if (c < H) {
        float a2[NPB], a3[NPB];
        float bb2 = b2[c], bbt = bt[c];
        #pragma unroll
        for (int n = 0; n < NPB; n++) { a2[n] = bb2; a3[n] = bbt; }
        const float4* w2r = (const float4*)(W2 + (size_t)c * H);
        const float4* wtr = (const float4*)(Wt + (size_t)c * H);
        #pragma unroll 5
        for (int k = 0; k < H4; k++) {
            float4 w2 = w2r[k], wt = wtr[k];
            #pragma unroll
            for (int n = 0; n < NPB; n++) {
                float4 v = *(const float4*)&vv[n * H + 4 * k];
                a2[n] = fmaf(v.x, w2.x, a2[n]); a2[n] = fmaf(v.y, w2.y, a2[n]);
                a2[n] = fmaf(v.z, w2.z, a2[n]); a2[n] = fmaf(v.w, w2.w, a2[n]);
                a3[n] = fmaf(v.x, wt.x, a3[n]); a3[n] = fmaf(v.y, wt.y, a3[n]);
                a3[n] = fmaf(v.z, wt.z, a3[n]); a3[n] = fmaf(v.w, wt.w, a3[n]);
            }
        }
        #pragma unroll
        for (int n = 0; n < NPB; n++) {
            d_m [(node0 + n) * H + c] = a2[n];
            d_vt[(node0 + n) * H + c] = a3[n];
        }
    }
}

// ------------------------------------------------------------------
// K4: per-batch light reductions -> d_sh (unchanged)
// ------------------------------------------------------------------
__global__ void k4_attn(const float* __restrict__ W1, const float* __restrict__ b1,
                        const float* __restrict__ qw, const float* __restrict__ qb,
                        const float* __restrict__ W3, const float* __restrict__ b3)
{
    int b = blockIdx.x;
    int t = threadIdx.x;
    __shared__ __align__(16) float sl[H];
    __shared__ float w1s[H];
    __shared__ float as[LSEQ * H];
    __shared__ float alpha[LSEQ];
    __shared__ __align__(16) float sg[H];

    if (t < H) sl[t] = d_v[(b * LSEQ + LSEQ - 1) * H + t];
    __syncthreads();

    if (t < H) {
        float acc = b1[t];
        const float4* w = (const float4*)(W1 + (size_t)t * H);
        for (int k = 0; k < H4; k++) {
            float4 wv = w[k];
            float4 s = *(const float4*)&sl[4 * k];
            acc = fmaf(s.x, wv.x, acc); acc = fmaf(s.y, wv.y, acc);
            acc = fmaf(s.z, wv.z, acc); acc = fmaf(s.w, wv.w, acc);
        }
        w1s[t] = acc;
    }
    __syncthreads();

    for (int idx = t; idx < LSEQ * H; idx += blockDim.x) {
        int l = idx / H, hh2 = idx - l * H;
        float pre = d_m[(b * LSEQ + l) * H + hh2];
        as[idx] = 1.f / (1.f + __expf(-(w1s[hh2] + pre)));
    }
    __syncthreads();

    if (t < LSEQ) {
        float acc = qb[0];
        for (int k = 0; k < H; k++) acc = fmaf(as[t * H + k], qw[k], acc);
        alpha[t] = acc;
    }
    __syncthreads();

    if (t < H) {
        float acc = 0.f;
        for (int l = 0; l < LSEQ; l++) acc = fmaf(alpha[l], d_v[(b * LSEQ + l) * H + t], acc);
        sg[t] = acc;
    }
    __syncthreads();

    if (t < H) {
        float acc = b3[t];
        const float4* w  = (const float4*)(W3 + (size_t)t * 2 * H);
        for (int k = 0; k < H4; k++) {
            float4 wv = w[k];
            float4 s = *(const float4*)&sl[4 * k];
            acc = fmaf(s.x, wv.x, acc); acc = fmaf(s.y, wv.y, acc);
            acc = fmaf(s.z, wv.z, acc); acc = fmaf(s.w, wv.w, acc);
        }
        for (int k = 0; k < H4; k++) {
            float4 wv = w[H4 + k];
            float4 s = *(const float4*)&sg[4 * k];
            acc = fmaf(s.x, wv.x, acc); acc = fmaf(s.y, wv.y, acc);
            acc = fmaf(s.z, wv.z, acc); acc = fmaf(s.w, wv.w, acc);
        }
        d_sh[b * H + t] = acc;
    }
}

// ------------------------------------------------------------------
// P1: int8 2-digit quantization of embed rows (warp per row).
// e = s*(q1 + q2/128), s = rowmax/127.
// ------------------------------------------------------------------
__global__ void p1_quant_embed(const float* __restrict__ embed)
{
    int warp = (blockIdx.x * blockDim.x + threadIdx.x) >> 5;
    int lane = threadIdx.x & 31;
    if (warp >= JPAD) return;
    float v[4];
    #pragma unroll
    for (int i = 0; i < 4; i++) {
        int k = lane + 32 * i;
        v[i] = (warp < NNODE && k < H) ? embed[(size_t)warp * H + k] : 0.f;
    }
    float m = fmaxf(fmaxf(fabsf(v[0]), fabsf(v[1])), fmaxf(fabsf(v[2]), fabsf(v[3])));
    #pragma unroll
    for (int o = 16; o; o >>= 1) m = fmaxf(m, __shfl_xor_sync(0xffffffffu, m, o));
    float inv = (m > 0.f) ? 127.f / m : 0.f;
    if (lane == 0) d_se[warp] = m * (1.f / 127.f);
    #pragma unroll
    for (int i = 0; i < 4; i++) {
        int k = lane + 32 * i;
        float t = v[i] * inv;
        int q1 = __float2int_rn(t);
        int q2 = __float2int_rn((t - (float)q1) * 128.f);
        d_e1[(size_t)warp * KPI + k] = (int8_t)q1;
        d_e2[(size_t)warp * KPI + k] = (int8_t)q2;
    }
}

// ------------------------------------------------------------------
// P2: quantize B rows (2048: vt|v) + sh rows (64). Warp per row.
// ------------------------------------------------------------------
__global__ void p2_quant_b()
{
    int rid = (blockIdx.x * blockDim.x + threadIdx.x) >> 5;
    int lane = threadIdx.x & 31;
    if (rid >= BATCH * 32 + BATCH) return;
    float v[4];
    #pragma unroll
    for (int i = 0; i < 4; i++) {
        int k = lane + 32 * i;
        float val = 0.f;
        if (k < H) {
            if (rid < BATCH * 32) {
                int b = rid >> 5, n = rid & 31;
                val = (n < 16) ? d_vt[(b * LSEQ + n) * H + k]
                               : d_v [(b * LSEQ + (n - 16)) * H + k];
            } else {
                val = d_sh[(rid - BATCH * 32) * H + k];
            }
        }
        v[i] = val;
    }
    float m = fmaxf(fmaxf(fabsf(v[0]), fabsf(v[1])), fmaxf(fabsf(v[2]), fabsf(v[3])));
    #pragma unroll
    for (int o = 16; o; o >>= 1) m = fmaxf(m, __shfl_xor_sync(0xffffffffu, m, o));
    float inv = (m > 0.f) ? 127.f / m : 0.f;
    float s = m * (1.f / 127.f);
    if (rid < BATCH * 32) {
        if (lane == 0) d_sb[rid] = s;
        #pragma unroll
        for (int i = 0; i < 4; i++) {
            int k = lane + 32 * i;
            float t = v[i] * inv;
            int q1 = __float2int_rn(t);
            int q2 = __float2int_rn((t - (float)q1) * 128.f);
            d_b1[(size_t)rid * KPI + k] = (int8_t)q1;
            d_b2[(size_t)rid * KPI + k] = (int8_t)q2;
        }
    } else {
        int b = rid - BATCH * 32;
        if (lane == 0) d_ssh[b] = s;
        #pragma unroll
        for (int i = 0; i < 4; i++) {
            int k = lane + 32 * i;
            float t = v[i] * inv;
            int q1 = __float2int_rn(t);
            int q2 = __float2int_rn((t - (float)q1) * 128.f);
            d_sh1[(size_t)b * KPI + k] = (int8_t)q1;
            d_sh2[(size_t)b * KPI + k] = (int8_t)q2;
        }
    }
}

// ------------------------------------------------------------------
// K5: int8 IMMA GEMM + softmax epilogue.
//   A digits (both) register-resident (32 regs). B digits via LDSM from
//   stride-144 smem; 3-deep cp.async pipeline; 3-product fixed-point:
//   dot = se*sb*(Dhi + Dmid/128), Dhi/Dmid exact s32.
// smem (bytes): [0,27648) 3 B buffers (dig1 4608 | dig2 4608 each);
//   [27648,60928) base 128x65 f32; [60928,69120) sb; [69120,69376) ssh.
// ------------------------------------------------------------------
#define SM_BBUF  0
#define BUFB     9216
#define SM_BASE  27648
#define SM_SB    60928
#define SM_SSH   69120
#define SMEM_K5  69376
#define BASE_STRIDE 65

#define DEQ(Dh, Dm, nt, i) \
    (__int2float_rn((Dh)[nt][i]) + __int2float_rn((Dm)[nt][i]) * 0.0078125f)

__global__ void __launch_bounds__(256, 2)
k5_imma(float* __restrict__ out)
{
    extern __shared__ __align__(16) char dsm[];
    uint32_t smb = smem_u32(dsm);
    float* s_base = (float*)(dsm + SM_BASE);

    int tid  = threadIdx.x;
    int wid  = tid >> 5;
    int lane = tid & 31;
    int grp  = lane >> 2;
    int qid  = lane & 3;
    int tile = blockIdx.x;

    // per-lane LDSM offset within a B tile (n-row + k-half select)
    uint32_t ldsm_off = ((lane & 7) + ((lane & 16) >> 1)) * BRSTR + ((lane & 8) << 1);

    // ---- A digit fragments, register-resident ----
    uint32_t A1[KSI][4], A2[KSI][4];
    int r0g = tile * MT + wid * 16 + grp;
    int r1g = r0g + 8;
    {
        const int8_t* e1a = d_e1 + (size_t)r0g * KPI;
        const int8_t* e1b = d_e1 + (size_t)r1g * KPI;
        const int8_t* e2a = d_e2 + (size_t)r0g * KPI;
        const int8_t* e2b = d_e2 + (size_t)r1g * KPI;
        #pragma unroll
        for (int ks = 0; ks < KSI; ks++) {
            int k0 = ks * 32 + 4 * qid;
            A1[ks][0] = *(const uint32_t*)(e1a + k0);
            A1[ks][1] = *(const uint32_t*)(e1b + k0);
            A1[ks][2] = *(const uint32_t*)(e1a + k0 + 16);
            A1[ks][3] = *(const uint32_t*)(e1b + k0 + 16);
            A2[ks][0] = *(const uint32_t*)(e2a + k0);
            A2[ks][1] = *(const uint32_t*)(e2b + k0);
            A2[ks][2] = *(const uint32_t*)(e2a + k0 + 16);
            A2[ks][3] = *(const uint32_t*)(e2b + k0 + 16);
        }
    }
    float se0 = d_se[r0g];
    float se1 = d_se[r1g];

    // ---- initial fills: SH digits (restride to 144), sb, ssh ----
    {
        // SH digits: 64 rows x 8 chunks x 2 digits = 1024 chunks
        for (int c = tid; c < 1024; c += 256) {
            int digit = c >> 9, r = (c >> 3) & 63, i = c & 7;
            uint32_t dst = smb + SM_BBUF + digit * 9216 + r * BRSTR + i * 16;
            const char* src = (digit ? (const char*)d_sh2 : (const char*)d_sh1)
                              + (size_t)r * KPI + i * 16;
            CP_ASYNC16(dst, src);
        }
        for (int c = tid; c < 512; c += 256)
            CP_ASYNC16(smb + SM_SB + c * 16, (const char*)d_sb + c * 16);
        if (tid < 16)
            CP_ASYNC16(smb + SM_SSH + tid * 16, (const char*)d_ssh + tid * 16);
        CP_COMMIT();
        CP_WAIT0();
    }
    __syncthreads();

    // ================= PHASE 0: base GEMM (E . SH^T), two passes =================
    const float* sshp = (const float*)(dsm + SM_SSH);
    int rl0 = wid * 16 + grp;
    #pragma unroll 1
    for (int pass = 0; pass < 2; pass++) {
        int Dh[4][4] = {}, Dm[4][4] = {};
        #pragma unroll
        for (int ks = 0; ks < KSI; ks++) {
            uint32_t q1A[4], q1B[4], q2A[4], q2B[4];
            uint32_t p0 = smb + SM_BBUF + pass * 4608 + ldsm_off + ks * 32;
            LDSM4(q1A[0], q1A[1], q1A[2], q1A[3], p0);
            LDSM4(q1B[0], q1B[1], q1B[2], q1B[3], p0 + 2304);
            LDSM4(q2A[0], q2A[1], q2A[2], q2A[3], p0 + 9216);
            LDSM4(q2B[0], q2B[1], q2B[2], q2B[3], p0 + 9216 + 2304);
            IMMA16832(Dh[0], A1[ks], q1A[0], q1A[1]);
            IMMA16832(Dh[1], A1[ks], q1A[2], q1A[3]);
            IMMA16832(Dh[2], A1[ks], q1B[0], q1B[1]);
            IMMA16832(Dh[3], A1[ks], q1B[2], q1B[3]);
            IMMA16832(Dm[0], A1[ks], q2A[0], q2A[1]);
            IMMA16832(Dm[1], A1[ks], q2A[2], q2A[3]);
            IMMA16832(Dm[2], A1[ks], q2B[0], q2B[1]);
            IMMA16832(Dm[3], A1[ks], q2B[2], q2B[3]);
            IMMA16832(Dm[0], A2[ks], q1A[0], q1A[1]);
            IMMA16832(Dm[1], A2[ks], q1A[2], q1A[3]);
            IMMA16832(Dm[2], A2[ks], q1B[0], q1B[1]);
            IMMA16832(Dm[3], A2[ks], q1B[2], q1B[3]);
        }
        #pragma unroll
        for (int nt = 0; nt < 4; nt++) {
            int c0 = pass * 32 + nt * 8 + 2 * qid;
            float sc0 = sshp[c0], sc1 = sshp[c0 + 1];
            s_base[rl0 * BASE_STRIDE + c0]           = se0 * sc0 * DEQ(Dh, Dm, nt, 0);
            s_base[rl0 * BASE_STRIDE + c0 + 1]       = se0 * sc1 * DEQ(Dh, Dm, nt, 1);
            s_base[(rl0 + 8) * BASE_STRIDE + c0]     = se1 * sc0 * DEQ(Dh, Dm, nt, 2);
            s_base[(rl0 + 8) * BASE_STRIDE + c0 + 1] = se1 * sc1 * DEQ(Dh, Dm, nt, 3);
        }
    }
    __syncthreads();     // phase 0 done; buffers can be reused

    // ---- prime cp.async pipeline: batches 0 and 1 ----
    #pragma unroll
    for (int pb = 0; pb < 2; pb++) {
        uint32_t bufb = smb + SM_BBUF + pb * BUFB;
        for (int c = tid; c < 512; c += 256) {
            int digit = c >> 8, r = (c >> 3) & 31, i = c & 7;
            uint32_t dst = bufb + digit * 4608 + r * BRSTR + i * 16;
            const char* src = (digit ? (const char*)d_b2 : (const char*)d_b1)
                              + ((size_t)pb * 32 + r) * KPI + i * 16;
            CP_ASYNC16(dst, src);
        }
        CP_COMMIT();
    }
    CP_WAIT1();
    __syncthreads();

    int j0 = tile * MT + rl0;
    int j1 = j0 + 8;

    #pragma unroll 1
    for (int b = 0; b < BATCH; b++) {
        uint32_t bufb = smb + SM_BBUF + (b % 3) * BUFB;

        int Dh[NTL][4] = {}, Dm[NTL][4] = {};
        #pragma unroll
        for (int ks = 0; ks < KSI; ks++) {
            uint32_t q1A[4], q1B[4], q2A[4], q2B[4];
            uint32_t p0 = bufb + ldsm_off + ks * 32;
            LDSM4(q1A[0], q1A[1], q1A[2], q1A[3], p0);
            LDSM4(q1B[0], q1B[1], q1B[2], q1B[3], p0 + 2304);
            LDSM4(q2A[0], q2A[1], q2A[2], q2A[3], p0 + 4608);
            LDSM4(q2B[0], q2B[1], q2B[2], q2B[3], p0 + 4608 + 2304);
            IMMA16832(Dh[0], A1[ks], q1A[0], q1A[1]);
            IMMA16832(Dh[1], A1[ks], q1A[2], q1A[3]);
            IMMA16832(Dh[2], A1[ks], q1B[0], q1B[1]);
            IMMA16832(Dh[3], A1[ks], q1B[2], q1B[3]);
            IMMA16832(Dm[0], A1[ks], q2A[0], q2A[1]);
            IMMA16832(Dm[1], A1[ks], q2A[2], q2A[3]);
            IMMA16832(Dm[2], A1[ks], q2B[0], q2B[1]);
            IMMA16832(Dm[3], A1[ks], q2B[2], q2B[3]);
            IMMA16832(Dm[0], A2[ks], q1A[0], q1A[1]);
            IMMA16832(Dm[1], A2[ks], q1A[2], q1A[3]);
            IMMA16832(Dm[2], A2[ks], q1B[0], q1B[1]);
            IMMA16832(Dm[3], A2[ks], q1B[2], q1B[3]);
        }

        // ---- prefetch batch b+2 (always commit a group) ----
        if (b + 2 < BATCH) {
            uint32_t dst0 = smb + SM_BBUF + ((b + 2) % 3) * BUFB;
            for (int c = tid; c < 512; c += 256) {
                int digit = c >> 8, r = (c >> 3) & 31, i = c & 7;
                uint32_t dst = dst0 + digit * 4608 + r * BRSTR + i * 16;
                const char* src = (digit ? (const char*)d_b2 : (const char*)d_b1)
                                  + ((size_t)(b + 2) * 32 + r) * KPI + i * 16;
                CP_ASYNC16(dst, src);
            }
        }
        CP_COMMIT();

        // ---- epilogue: dequant, no-max softmax, base add ----
        {
            const float* sbp = (const float*)(dsm + SM_SB) + b * 32 + 2 * qid;
            float2 sP0 = *(const float2*)(sbp);
            float2 sP1 = *(const float2*)(sbp + 8);
            float2 sC0 = *(const float2*)(sbp + 16);
            float2 sC1 = *(const float2*)(sbp + 24);

            float base0 = s_base[rl0 * BASE_STRIDE + b];
            float base1 = s_base[(rl0 + 8) * BASE_STRIDE + b];

            // row 0
            float e00 = __expf(se0 * sP0.x * DEQ(Dh, Dm, 0, 0));
            float e01 = __expf(se0 * sP0.y * DEQ(Dh, Dm, 0, 1));
            float e10 = __expf(se0 * sP1.x * DEQ(Dh, Dm, 1, 0));
            float e11 = __expf(se0 * sP1.y * DEQ(Dh, Dm, 1, 1));
            float c00 = se0 * sC0.x * DEQ(Dh, Dm, 2, 0);
            float c01 = se0 * sC0.y * DEQ(Dh, Dm, 2, 1);
            float c10 = se0 * sC1.x * DEQ(Dh, Dm, 3, 0);
            float c11 = se0 * sC1.y * DEQ(Dh, Dm, 3, 1);
            float es0 = (e00 + e01) + (e10 + e11);
            float ws0 = fmaf(e00, c00, fmaf(e01, c01, fmaf(e10, c10, e11 * c11)));

            // row 1
            float f00 = __expf(se1 * sP0.x * DEQ(Dh, Dm, 0, 2));
            float f01 = __expf(se1 * sP0.y * DEQ(Dh, Dm, 0, 3));
            float f10 = __expf(se1 * sP1.x * DEQ(Dh, Dm, 1, 2));
            float f11 = __expf(se1 * sP1.y * DEQ(Dh, Dm, 1, 3));
            float g00 = se1 * sC0.x * DEQ(Dh, Dm, 2, 2);
            float g01 = se1 * sC0.y * DEQ(Dh, Dm, 2, 3);
            float g10 = se1 * sC1.x * DEQ(Dh, Dm, 3, 2);
            float g11 = se1 * sC1.y * DEQ(Dh, Dm, 3, 3);
            float es1 = (f00 + f01) + (f10 + f11);
            float ws1 = fmaf(f00, g00, fmaf(f01, g01, fmaf(f10, g10, f11 * g11)));

            es0 += __shfl_xor_sync(0xffffffffu, es0, 1);
            ws0 += __shfl_xor_sync(0xffffffffu, ws0, 1);
            es1 += __shfl_xor_sync(0xffffffffu, es1, 1);
            ws1 += __shfl_xor_sync(0xffffffffu, ws1, 1);
            es0 += __shfl_xor_sync(0xffffffffu, es0, 2);
            ws0 += __shfl_xor_sync(0xffffffffu, ws0, 2);
            es1 += __shfl_xor_sync(0xffffffffu, es1, 2);
            ws1 += __shfl_xor_sync(0xffffffffu, ws1, 2);

            if (qid == 0) {
                if (j0 < NNODE) out[(size_t)b * NNODE + j0] = base0 + ws0 / es0;
                if (j1 < NNODE) out[(size_t)b * NNODE + j1] = base1 + ws1 / es1;
            }
        }

        CP_WAIT1();
        __syncthreads();
    }
}

// ------------------------------------------------------------------
extern "C" void kernel_launch(void* const* d_in, const int* in_sizes, int n_in,
                              void* d_out, int out_size)
{
    const int*   x     = (const int*)  d_in[0];
    const int*   ei    = (const int*)  d_in[1];
    const float* ew    = (const float*)d_in[2];
    // d_in[3] = batch (unused)
    const float* embed = (const float*)d_in[4];
    const float* ggc   = (const float*)d_in[5];
    const float* wih   = (const float*)d_in[6];
    const float* whh   = (const float*)d_in[7];
    const float* bih   = (const float*)d_in[8];
    const float* bhh   = (const float*)d_in[9];
    const float* W1    = (const float*)d_in[10];
    const float* b1    = (const float*)d_in[11];
    const float* W2    = (const float*)d_in[12];
    const float* b2    = (const float*)d_in[13];
    const float* Wt    = (const float*)d_in[14];
    const float* bt    = (const float*)d_in[15];
    const float* qw    = (const float*)d_in[16];
    const float* qb    = (const float*)d_in[17];
    const float* W3    = (const float*)d_in[18];
    const float* b3    = (const float*)d_in[19];
    float* out = (float*)d_out;

    cudaFuncSetAttribute(k5_imma, cudaFuncAttributeMaxDynamicSharedMemorySize, SMEM_K5);

    k1_gather_m<<<NNODES, 128>>>(x, embed, ggc);
    k2_scatter <<<(EDGES * H + 255) / 256, 256>>>(ei, ew);
    p1_quant_embed<<<JPAD / 4, 128>>>(embed);
    k3_gru_post<<<NNODES / NPB, 128>>>(wih, whh, bih, bhh, W2, b2, Wt, bt);
    k4_attn    <<<BATCH, 128>>>(W1, b1, qw, qb, W3, b3);
    p2_quant_b <<<(BATCH * 32 + BATCH + 3) / 4, 128>>>();
    k5_imma    <<<NTILES, 256, SMEM_K5>>>(out);
}

// round 12
// speedup vs baseline: 3.2514x; 3.2514x over previous
#include <cuda_runtime.h>
#include <cuda_bf16.h>
#include <math.h>
#include <cstdint>

#define H       100
#define NNODES  1024    // N = B*L
#define BATCH   64
#define LSEQ    16
#define EDGES   2048
#define NNODE   40000
#define H4      25
#define NPB     2       // nodes per block in k3

// ---- mma.sync GEMM config ----
#define MT      128                // j rows per CTA (8 warps x m16)
#define NTILES  313                // ceil(40000/128)
#define JPAD    (NTILES * MT)      // 40064
#define KP      112                // padded K (7 k-steps of 16)
#define KSTEPS  7
#define BROWS   32                 // B rows per batch: 16 vt | 16 v
#define BSTRIDE 120                // row stride in bf16
#define NTL     4                  // n8 tiles per batch: 16 P + 16 C
#define BCH     8                  // batches per CTA chunk
#define NBY     (BATCH / BCH)      // 8 y-chunks

typedef unsigned long long ull;

#define MMA16816(d, a, b0, b1)                                              \
    asm volatile("mma.sync.aligned.m16n8k16.row.col.f32.bf16.bf16.f32 "     \
        "{%0,%1,%2,%3}, {%4,%5,%6,%7}, {%8,%9}, {%0,%1,%2,%3};"             \
        : "+f"((d)[0]), "+f"((d)[1]), "+f"((d)[2]), "+f"((d)[3])            \
        : "r"((a)[0]), "r"((a)[1]), "r"((a)[2]), "r"((a)[3]),               \
          "r"(b0), "r"(b1))

#define LDSM4(r0, r1, r2, r3, addr)                                         \
    asm volatile("ldmatrix.sync.aligned.m8n8.x4.shared.b16 {%0,%1,%2,%3}, [%4];" \
        : "=r"(r0), "=r"(r1), "=r"(r2), "=r"(r3) : "r"(addr))

#define CP_ASYNC16(smaddr, gptr)                                            \
    asm volatile("cp.async.cg.shared.global [%0], [%1], 16;"                \
        :: "r"(smaddr), "l"(gptr) : "memory")
#define CP_COMMIT()  asm volatile("cp.async.commit_group;" ::: "memory")
#define CP_WAIT1()   asm volatile("cp.async.wait_group 1;" ::: "memory")
#define CP_WAIT0()   asm volatile("cp.async.wait_group 0;" ::: "memory")

static __device__ __forceinline__ uint32_t smem_u32(const void* p) {
    uint32_t a;
    asm("{ .reg .u64 t; cvta.to.shared.u64 t, %1; cvt.u32.u64 %0, t; }" : "=r"(a) : "l"(p));
    return a;
}

// ---- scratch (no allocations allowed) ----
__device__ float d_h  [NNODES * H];
__device__ float d_m  [NNODES * H];
__device__ float d_agg[NNODES * H];
__device__ float d_v  [NNODES * H];
__device__ float d_vt [NNODES * H];
__device__ float d_sh [BATCH  * H];
// bf16 hi/lo split operands
__device__ __nv_bfloat16 d_ehi[(size_t)JPAD * KP];
__device__ __nv_bfloat16 d_elo[(size_t)JPAD * KP];
__device__ __nv_bfloat16 d_bhi[BATCH * BROWS * BSTRIDE];
__device__ __nv_bfloat16 d_blo[BATCH * BROWS * BSTRIDE];
__device__ __nv_bfloat16 d_shhi[BATCH * BSTRIDE];
__device__ __nv_bfloat16 d_shlo[BATCH * BSTRIDE];

// ------------------------------------------------------------------
// K1: h = embed[x];  m = h @ ggc_w[0];  agg = 0
// ------------------------------------------------------------------
__global__ void k1_gather_m(const int* __restrict__ x,
                            const float* __restrict__ embed,
                            const float* __restrict__ ggc)
{
    int i = blockIdx.x;
    int t = threadIdx.x;
    __shared__ float hs[H];
    int xi = x[i];
    if (t < H) {
        float val = embed[(size_t)xi * H + t];
        hs[t] = val;
        d_h[i * H + t] = val;
    }
    __syncthreads();
    if (t < H) {
        float acc = 0.f;
        #pragma unroll 4
        for (int k = 0; k < H; k++)
            acc = fmaf(hs[k], ggc[k * H + t], acc);
        d_m[i * H + t]   = acc;
        d_agg[i * H + t] = 0.f;
    }
}

// ------------------------------------------------------------------
// K2: agg[dst] += w_e * m[src]
// ------------------------------------------------------------------
__global__ void k2_scatter(const int* __restrict__ ei,
                           const float* __restrict__ ew)
{
    int idx = blockIdx.x * blockDim.x + threadIdx.x;
    if (idx >= EDGES * H) return;
    int e = idx / H;
    int h = idx - e * H;
    int src = ei[e];
    int dst = ei[EDGES + e];
    atomicAdd(&d_agg[dst * H + h], ew[e] * d_m[src * H + h]);
}

// ------------------------------------------------------------------
// K3: GRU + fused W2-pre/vt. NPB=2 -> 512 CTAs. (R9 exact version)
// ------------------------------------------------------------------
__global__ void __launch_bounds__(128)
k3_gru_post(const float* __restrict__ wih,
            const float* __restrict__ whh,
            const float* __restrict__ bih,
            const float* __restrict__ bhh,
            const float* __restrict__ W2,
            const float* __restrict__ b2,
            const float* __restrict__ Wt,
            const float* __restrict__ bt)
{
    int node0 = blockIdx.x * NPB;
    int c = threadIdx.x;
    __shared__ __align__(16) float ag[NPB * H];
    __shared__ __align__(16) float hh[NPB * H];
    __shared__ __align__(16) float vv[NPB * H];

    for (int idx = c; idx < NPB * H; idx += 128) {
        ag[idx] = d_agg[node0 * H + idx];
        hh[idx] = d_h  [node0 * H + idx];
    }
    __syncthreads();

    if (c < H) {
        float air[NPB], aiz[NPB], ain[NPB], ahr[NPB], ahz[NPB], ahn[NPB];
        float br = bih[c], bz = bih[H + c], bn = bih[2 * H + c];
        float cr = bhh[c], cz = bhh[H + c], cn = bhh[2 * H + c];
        #pragma unroll
        for (int n = 0; n < NPB; n++) {
            air[n] = br; aiz[n] = bz; ain[n] = bn;
            ahr[n] = cr; ahz[n] = cz; ahn[n] = cn;
        }
        const float4* wr4 = (const float4*)(wih + (size_t)c * H);
        const float4* wz4 = (const float4*)(wih + (size_t)(H + c) * H);
        const float4* wn4 = (const float4*)(wih + (size_t)(2 * H + c) * H);
        const float4* ur4 = (const float4*)(whh + (size_t)c * H);
        const float4* uz4 = (const float4*)(whh + (size_t)(H + c) * H);
        const float4* un4 = (const float4*)(whh + (size_t)(2 * H + c) * H);

        for (int k = 0; k < H4; k++) {
            float4 wr = wr4[k], wz = wz4[k], wn = wn4[k];
            float4 ur = ur4[k], uz = uz4[k], un = un4[k];
            #pragma unroll
            for (int n = 0; n < NPB; n++) {
                float4 a  = *(const float4*)&ag[n * H + 4 * k];
                float4 hv = *(const float4*)&hh[n * H + 4 * k];
                air[n] = fmaf(a.x, wr.x, air[n]); air[n] = fmaf(a.y, wr.y, air[n]);
                air[n] = fmaf(a.z, wr.z, air[n]); air[n] = fmaf(a.w, wr.w, air[n]);
                aiz[n] = fmaf(a.x, wz.x, aiz[n]); aiz[n] = fmaf(a.y, wz.y, aiz[n]);
                aiz[n] = fmaf(a.z, wz.z, aiz[n]); aiz[n] = fmaf(a.w, wz.w, aiz[n]);
                ain[n] = fmaf(a.x, wn.x, ain[n]); ain[n] = fmaf(a.y, wn.y, ain[n]);
                ain[n] = fmaf(a.z, wn.z, ain[n]); ain[n] = fmaf(a.w, wn.w, ain[n]);
                ahr[n] = fmaf(hv.x, ur.x, ahr[n]); ahr[n] = fmaf(hv.y, ur.y, ahr[n]);
                ahr[n] = fmaf(hv.z, ur.z, ahr[n]); ahr[n] = fmaf(hv.w, ur.w, ahr[n]);
                ahz[n] = fmaf(hv.x, uz.x, ahz[n]); ahz[n] = fmaf(hv.y, uz.y, ahz[n]);
                ahz[n] = fmaf(hv.z, uz.z, ahz[n]); ahz[n] = fmaf(hv.w, uz.w, ahz[n]);
                ahn[n] = fmaf(hv.x, un.x, ahn[n]); ahn[n] = fmaf(hv.y, un.y, ahn[n]);
                ahn[n] = fmaf(hv.z, un.z, ahn[n]); ahn[n] = fmaf(hv.w, un.w, ahn[n]);
            }
        }
        #pragma unroll
        for (int n = 0; n < NPB; n++) {
            float r  = 1.f / (1.f + __expf(-(air[n] + ahr[n])));
            float zg = 1.f / (1.f + __expf(-(aiz[n] + ahz[n])));
            float ng = tanhf(ain[n] + r * ahn[n]);
            float nv = (1.f - zg) * ng + zg * hh[n * H + c];
            vv[n * H + c] = nv;
            d_v[(node0 + n) * H + c] = nv;
        }
    }
    __syncthreads();

    if (c < H) {
        float a2[NPB], a3[NPB];
        float bb2 = b2[c], bbt = bt[c];
        #pragma unroll
        for (int n = 0; n < NPB; n++) { a2[n] = bb2; a3[n] = bbt; }
        const float4* w2r = (const float4*)(W2 + (size_t)c * H);
        const float4* wtr = (const float4*)(Wt + (size_t)c * H);
        for (int k = 0; k < H4; k++) {
            float4 w2 = w2r[k], wt = wtr[k];
            #pragma unroll
            for (int n = 0; n < NPB; n++) {
                float4 v = *(const float4*)&vv[n * H + 4 * k];
                a2[n] = fmaf(v.x, w2.x, a2[n]); a2[n] = fmaf(v.y, w2.y, a2[n]);
                a2[n] = fmaf(v.z, w2.z, a2[n]); a2[n] = fmaf(v.w, w2.w, a2[n]);
                a3[n] = fmaf(v.x, wt.x, a3[n]); a3[n] = fmaf(v.y, wt.y, a3[n]);
                a3[n] = fmaf(v.z, wt.z, a3[n]); a3[n] = fmaf(v.w, wt.w, a3[n]);
            }
        }
        #pragma unroll
        for (int n = 0; n < NPB; n++) {
            d_m [(node0 + n) * H + c] = a2[n];
            d_vt[(node0 + n) * H + c] = a3[n];
        }
    }
}

// ------------------------------------------------------------------
// K4: per-batch light reductions -> d_sh (unchanged)
// ------------------------------------------------------------------
__global__ void k4_attn(const float* __restrict__ W1, const float* __restrict__ b1,
                        const float* __restrict__ qw, const float* __restrict__ qb,
                        const float* __restrict__ W3, const float* __restrict__ b3)
{
    int b = blockIdx.x;
    int t = threadIdx.x;
    __shared__ __align__(16) float sl[H];
    __shared__ float w1s[H];
    __shared__ float as[LSEQ * H];
    __shared__ float alpha[LSEQ];
    __shared__ __align__(16) float sg[H];

    if (t < H) sl[t] = d_v[(b * LSEQ + LSEQ - 1) * H + t];
    __syncthreads();

    if (t < H) {
        float acc = b1[t];
        const float4* w = (const float4*)(W1 + (size_t)t * H);
        for (int k = 0; k < H4; k++) {
            float4 wv = w[k];
            float4 s = *(const float4*)&sl[4 * k];
            acc = fmaf(s.x, wv.x, acc); acc = fmaf(s.y, wv.y, acc);
            acc = fmaf(s.z, wv.z, acc); acc = fmaf(s.w, wv.w, acc);
        }
        w1s[t] = acc;
    }
    __syncthreads();

    for (int idx = t; idx < LSEQ * H; idx += blockDim.x) {
        int l = idx / H, hh2 = idx - l * H;
        float pre = d_m[(b * LSEQ + l) * H + hh2];
        as[idx] = 1.f / (1.f + __expf(-(w1s[hh2] + pre)));
    }
    __syncthreads();

    if (t < LSEQ) {
        float acc = qb[0];
        for (int k = 0; k < H; k++) acc = fmaf(as[t * H + k], qw[k], acc);
        alpha[t] = acc;
    }
    __syncthreads();

    if (t < H) {
        float acc = 0.f;
        for (int l = 0; l < LSEQ; l++) acc = fmaf(alpha[l], d_v[(b * LSEQ + l) * H + t], acc);
        sg[t] = acc;
    }
    __syncthreads();

    if (t < H) {
        float acc = b3[t];
        const float4* w  = (const float4*)(W3 + (size_t)t * 2 * H);
        for (int k = 0; k < H4; k++) {
            float4 wv = w[k];
            float4 s = *(const float4*)&sl[4 * k];
            acc = fmaf(s.x, wv.x, acc); acc = fmaf(s.y, wv.y, acc);
            acc = fmaf(s.z, wv.z, acc); acc = fmaf(s.w, wv.w, acc);
        }
        for (int k = 0; k < H4; k++) {
            float4 wv = w[H4 + k];
            float4 s = *(const float4*)&sg[4 * k];
            acc = fmaf(s.x, wv.x, acc); acc = fmaf(s.y, wv.y, acc);
            acc = fmaf(s.z, wv.z, acc); acc = fmaf(s.w, wv.w, acc);
        }
        d_sh[b * H + t] = acc;
    }
}

// ------------------------------------------------------------------
// P1: bf16 hi/lo split of embed -> [JPAD, KP], zero-padded
// ------------------------------------------------------------------
__global__ void p1_split_embed(const float* __restrict__ embed)
{
    int idx = blockIdx.x * blockDim.x + threadIdx.x;
    if (idx >= JPAD * KP) return;
    int row = idx / KP, k = idx - row * KP;
    float val = (row < NNODE && k < H) ? embed[(size_t)row * H + k] : 0.f;
    __nv_bfloat16 hi = __float2bfloat16(val);
    d_ehi[idx] = hi;
    d_elo[idx] = __float2bfloat16(val - __bfloat162float(hi));
}

// ------------------------------------------------------------------
// P2: B rows [b][n][k]: n<16 -> vt, else v;  plus sh tile [b][k]
// ------------------------------------------------------------------
__global__ void p2_split_b()
{
    int idx = blockIdx.x * blockDim.x + threadIdx.x;
    int nb = BATCH * BROWS * BSTRIDE;
    if (idx < nb) {
        int k = idx % BSTRIDE;
        int r = idx / BSTRIDE;
        int n = r % BROWS;
        int b = r / BROWS;
        float val = 0.f;
        if (k < H)
            val = (n < 16) ? d_vt[(b * LSEQ + n) * H + k]
                           : d_v [(b * LSEQ + (n - 16)) * H + k];
        __nv_bfloat16 hi = __float2bfloat16(val);
        d_bhi[idx] = hi;
        d_blo[idx] = __float2bfloat16(val - __bfloat162float(hi));
    } else {
        int i2 = idx - nb;
        if (i2 < BATCH * BSTRIDE) {
            int k = i2 % BSTRIDE;
            int b = i2 / BSTRIDE;
            float val = (k < H) ? d_sh[b * H + k] : 0.f;
            __nv_bfloat16 hi = __float2bfloat16(val);
            d_shhi[i2] = hi;
            d_shlo[i2] = __float2bfloat16(val - __bfloat162float(hi));
        }
    }
}

// ------------------------------------------------------------------
// K5: HMMA GEMM + softmax epilogue, batch-split grid (313, 8).
//   Each CTA: 128 j-rows x 8 batches. A-hi frags register-resident;
//   A-lo via ldmatrix; B frags via ldmatrix; 3-deep cp.async pipeline;
//   phase 0 computes only this chunk's 8 base columns.
// smem (bytes):
//   [0, 46080)       3 B buffers (hi 7680 | lo 7680 each)
//   [46080, 76800)   A-lo tile 128 x 120 bf16
//   [76800, 81408)   base floats 128 x 9
// ------------------------------------------------------------------
#define SM_BBUF  0
#define BUFB     15360
#define SM_ALO   46080
#define SM_BASE  76800
#define SMEM_K5  81408
#define BASE_STRIDE 9
#define BQ1      (BROWS * BSTRIDE)   // 3840 bf16 per split per batch

__global__ void __launch_bounds__(256, 2)
k5_hmma(float* __restrict__ out)
{
    extern __shared__ __align__(16) char dsm[];
    uint32_t smb = smem_u32(dsm);
    float* s_base = (float*)(dsm + SM_BASE);

    int tid  = threadIdx.x;
    int wid  = tid >> 5;
    int lane = tid & 31;
    int grp  = lane >> 2;
    int qid  = lane & 3;
    int tile = blockIdx.x;
    int b0   = blockIdx.y * BCH;

    // ---- A-hi fragments, register-resident ----
    uint32_t ahi[KSTEPS][4];
    {
        int r0 = tile * MT + wid * 16 + grp;
        int r1 = r0 + 8;
        #pragma unroll
        for (int ks = 0; ks < KSTEPS; ks++) {
            int k0 = ks * 16 + 2 * qid;
            ahi[ks][0] = *(const uint32_t*)(d_ehi + (size_t)r0 * KP + k0);
            ahi[ks][1] = *(const uint32_t*)(d_ehi + (size_t)r1 * KP + k0);
            ahi[ks][2] = *(const uint32_t*)(d_ehi + (size_t)r0 * KP + k0 + 8);
            ahi[ks][3] = *(const uint32_t*)(d_ehi + (size_t)r1 * KP + k0 + 8);
        }
    }

    // ---- stage A-lo tile (128 x 112 bf16, stride 120) + sh rows ----
    {
        const __nv_bfloat16* src = d_elo + (size_t)tile * MT * KP;
        for (int c = tid; c < MT * 14; c += 256) {
            int row = c / 14, cc = c - row * 14;
            uint32_t dst = smb + SM_ALO + row * 240 + cc * 16;
            CP_ASYNC16(dst, (const char*)(src + (size_t)row * KP) + cc * 16);
        }
        // sh rows [b0, b0+8): 8 x 240B = 120 chunks per digit, contiguous
        for (int c = tid; c < 120; c += 256) {
            uint32_t dst = smb + SM_BBUF + c * 16;
            CP_ASYNC16(dst, (const char*)(d_shhi + (size_t)b0 * BSTRIDE) + c * 16);
            CP_ASYNC16(dst + 7680, (const char*)(d_shlo + (size_t)b0 * BSTRIDE) + c * 16);
        }
        CP_COMMIT();
        CP_WAIT0();
    }
    __syncthreads();

    uint32_t alo_addr = smb + SM_ALO + (wid * 16 + (lane & 15)) * 240
                        + ((lane >> 4) * 8) * 2;
    uint32_t brow_off = lane * 240;

    int rl0 = wid * 16 + grp;

    // ===== PHASE 0: base GEMM for this chunk's 8 columns =====
    {
        const __nv_bfloat16* Bh = (const __nv_bfloat16*)(dsm + SM_BBUF);
        const __nv_bfloat16* Bl = (const __nv_bfloat16*)(dsm + SM_BBUF + 7680);
        float Db[4] = {0.f, 0.f, 0.f, 0.f};
        #pragma unroll
        for (int ks = 0; ks < KSTEPS; ks++) {
            int kb = ks * 16 + 2 * qid;
            uint32_t al[4];
            LDSM4(al[0], al[1], al[2], al[3], alo_addr + ks * 32);
            int n = grp;
            uint32_t bh0 = *(const uint32_t*)(Bh + n * BSTRIDE + kb);
            uint32_t bh1 = *(const uint32_t*)(Bh + n * BSTRIDE + kb + 8);
            uint32_t bl0 = *(const uint32_t*)(Bl + n * BSTRIDE + kb);
            uint32_t bl1 = *(const uint32_t*)(Bl + n * BSTRIDE + kb + 8);
            MMA16816(Db, ahi[ks], bh0, bh1);
            MMA16816(Db, ahi[ks], bl0, bl1);
            MMA16816(Db, al,      bh0, bh1);
        }
        int c0 = 2 * qid;
        s_base[rl0 * BASE_STRIDE + c0]           = Db[0];
        s_base[rl0 * BASE_STRIDE + c0 + 1]       = Db[1];
        s_base[(rl0 + 8) * BASE_STRIDE + c0]     = Db[2];
        s_base[(rl0 + 8) * BASE_STRIDE + c0 + 1] = Db[3];
        __syncthreads();
    }

    // ---- prime cp.async pipeline: local batches 0 and 1 ----
    #pragma unroll
    for (int pb = 0; pb < 2; pb++) {
        uint32_t dst = smb + SM_BBUF + pb * BUFB;
        const char* sh = (const char*)(d_bhi + (size_t)(b0 + pb) * BQ1);
        const char* sl = (const char*)(d_blo + (size_t)(b0 + pb) * BQ1);
        for (int c = tid; c < 480; c += 256) {
            CP_ASYNC16(dst + c * 16, sh + c * 16);
            CP_ASYNC16(dst + 7680 + c * 16, sl + c * 16);
        }
        CP_COMMIT();
    }
    CP_WAIT1();
    __syncthreads();

    int j0 = tile * MT + rl0;
    int j1 = j0 + 8;

    #pragma unroll 1
    for (int b = 0; b < BCH; b++) {
        int bg = b0 + b;
        uint32_t bufb = smb + SM_BBUF + (b % 3) * BUFB;

        // ---- MMA mainloop ----
        float D[NTL][4];
        #pragma unroll
        for (int nt = 0; nt < NTL; nt++)
            { D[nt][0] = 0.f; D[nt][1] = 0.f; D[nt][2] = 0.f; D[nt][3] = 0.f; }

        #pragma unroll
        for (int ks = 0; ks < KSTEPS; ks++) {
            uint32_t al[4], bh0[4], bh1[4], bl0[4], bl1[4];
            LDSM4(al[0], al[1], al[2], al[3], alo_addr + ks * 32);
            LDSM4(bh0[0], bh0[1], bh0[2], bh0[3], bufb + brow_off + ks * 32);
            LDSM4(bh1[0], bh1[1], bh1[2], bh1[3], bufb + brow_off + ks * 32 + 16);
            LDSM4(bl0[0], bl0[1], bl0[2], bl0[3], bufb + 7680 + brow_off + ks * 32);
            LDSM4(bl1[0], bl1[1], bl1[2], bl1[3], bufb + 7680 + brow_off + ks * 32 + 16);
            #pragma unroll
            for (int nt = 0; nt < NTL; nt++) MMA16816(D[nt], ahi[ks], bh0[nt], bh1[nt]);
            #pragma unroll
            for (int nt = 0; nt < NTL; nt++) MMA16816(D[nt], ahi[ks], bl0[nt], bl1[nt]);
            #pragma unroll
            for (int nt = 0; nt < NTL; nt++) MMA16816(D[nt], al,      bh0[nt], bh1[nt]);
        }

        // ---- prefetch local batch b+2 (always commit a group) ----
        if (b + 2 < BCH) {
            uint32_t dst = smb + SM_BBUF + ((b + 2) % 3) * BUFB;
            const char* sh = (const char*)(d_bhi + (size_t)(bg + 2) * BQ1);
            const char* sl = (const char*)(d_blo + (size_t)(bg + 2) * BQ1);
            for (int c = tid; c < 480; c += 256) {
                CP_ASYNC16(dst + c * 16, sh + c * 16);
                CP_ASYNC16(dst + 7680 + c * 16, sl + c * 16);
            }
        }
        CP_COMMIT();

        // ---- epilogue (no-max softmax; logits are O(1) here) ----
        {
            float base0 = s_base[rl0 * BASE_STRIDE + b];
            float base1 = s_base[(rl0 + 8) * BASE_STRIDE + b];

            float e00 = __expf(D[0][0]), e01 = __expf(D[0][1]);
            float e10 = __expf(D[1][0]), e11 = __expf(D[1][1]);
            float es0 = (e00 + e01) + (e10 + e11);
            float ws0 = fmaf(e00, D[2][0], fmaf(e01, D[2][1],
                        fmaf(e10, D[3][0], e11 * D[3][1])));

            float f00 = __expf(D[0][2]), f01 = __expf(D[0][3]);
            float f10 = __expf(D[1][2]), f11 = __expf(D[1][3]);
            float es1 = (f00 + f01) + (f10 + f11);
            float ws1 = fmaf(f00, D[2][2], fmaf(f01, D[2][3],
                        fmaf(f10, D[3][2], f11 * D[3][3])));

            es0 += __shfl_xor_sync(0xffffffffu, es0, 1);
            ws0 += __shfl_xor_sync(0xffffffffu, ws0, 1);
            es1 += __shfl_xor_sync(0xffffffffu, es1, 1);
            ws1 += __shfl_xor_sync(0xffffffffu, ws1, 1);
            es0 += __shfl_xor_sync(0xffffffffu, es0, 2);
            ws0 += __shfl_xor_sync(0xffffffffu, ws0, 2);
            es1 += __shfl_xor_sync(0xffffffffu, es1, 2);
            ws1 += __shfl_xor_sync(0xffffffffu, ws1, 2);

            if (qid == 0) {
                if (j0 < NNODE) out[(size_t)bg * NNODE + j0] = base0 + ws0 / es0;
                if (j1 < NNODE) out[(size_t)bg * NNODE + j1] = base1 + ws1 / es1;
            }
        }

        CP_WAIT1();
        __syncthreads();
    }
}

// ------------------------------------------------------------------
extern "C" void kernel_launch(void* const* d_in, const int* in_sizes, int n_in,
                              void* d_out, int out_size)
{
    const int*   x     = (const int*)  d_in[0];
    const int*   ei    = (const int*)  d_in[1];
    const float* ew    = (const float*)d_in[2];
    // d_in[3] = batch (unused)
    const float* embed = (const float*)d_in[4];
    const float* ggc   = (const float*)d_in[5];
    const float* wih   = (const float*)d_in[6];
    const float* whh   = (const float*)d_in[7];
    const float* bih   = (const float*)d_in[8];
    const float* bhh   = (const float*)d_in[9];
    const float* W1    = (const float*)d_in[10];
    const float* b1    = (const float*)d_in[11];
    const float* W2    = (const float*)d_in[12];
    const float* b2    = (const float*)d_in[13];
    const float* Wt    = (const float*)d_in[14];
    const float* bt    = (const float*)d_in[15];
    const float* qw    = (const float*)d_in[16];
    const float* qb    = (const float*)d_in[17];
    const float* W3    = (const float*)d_in[18];
    const float* b3    = (const float*)d_in[19];
    float* out = (float*)d_out;

    cudaFuncSetAttribute(k5_hmma, cudaFuncAttributeMaxDynamicSharedMemorySize, SMEM_K5);

    k1_gather_m<<<NNODES, 128>>>(x, embed, ggc);
    k2_scatter <<<(EDGES * H + 255) / 256, 256>>>(ei, ew);
    p1_split_embed<<<(JPAD * KP + 255) / 256, 256>>>(embed);
    k3_gru_post<<<NNODES / NPB, 128>>>(wih, whh, bih, bhh, W2, b2, Wt, bt);
    k4_attn    <<<BATCH, 128>>>(W1, b1, qw, qb, W3, b3);
    p2_split_b <<<(BATCH * BROWS * BSTRIDE + BATCH * BSTRIDE + 255) / 256, 256>>>();
    dim3 g5(NTILES, NBY);
    k5_hmma    <<<g5, 256, SMEM_K5>>>(out);
}

// round 14
// speedup vs baseline: 3.2634x; 1.0037x over previous
#include <cuda_runtime.h>
#include <cuda_bf16.h>
#include <math.h>
#include <cstdint>

#define H       100
#define NNODES  1024    // N = B*L
#define BATCH   64
#define LSEQ    16
#define EDGES   2048
#define NNODE   40000
#define H4      25
#define NPB     2       // nodes per block in k3

// ---- mma.sync GEMM config ----
#define MT      128                // j rows per CTA (8 warps x m16)
#define NTILES  313                // ceil(40000/128)
#define JPAD    (NTILES * MT)      // 40064
#define KP      112                // padded K (7 k-steps of 16)
#define KSTEPS  7
#define BROWS   32                 // B rows per batch: 16 vt | 16 v
#define BSTRIDE 120                // row stride in bf16
#define NTL     4                  // n8 tiles per batch: 16 P + 16 C
#define BCH     8                  // batches per CTA chunk
#define NBY     (BATCH / BCH)      // 8 y-chunks

#define P1BLKS  ((JPAD * KP) / 256)   // 17528 p1 blocks in merged kernel

typedef unsigned long long ull;

#define MMA16816(d, a, b0, b1)                                              \
    asm volatile("mma.sync.aligned.m16n8k16.row.col.f32.bf16.bf16.f32 "     \
        "{%0,%1,%2,%3}, {%4,%5,%6,%7}, {%8,%9}, {%0,%1,%2,%3};"             \
        : "+f"((d)[0]), "+f"((d)[1]), "+f"((d)[2]), "+f"((d)[3])            \
        : "r"((a)[0]), "r"((a)[1]), "r"((a)[2]), "r"((a)[3]),               \
          "r"(b0), "r"(b1))

#define LDSM4(r0, r1, r2, r3, addr)                                         \
    asm volatile("ldmatrix.sync.aligned.m8n8.x4.shared.b16 {%0,%1,%2,%3}, [%4];" \
        : "=r"(r0), "=r"(r1), "=r"(r2), "=r"(r3) : "r"(addr))

#define CP_ASYNC16(smaddr, gptr)                                            \
    asm volatile("cp.async.cg.shared.global [%0], [%1], 16;"                \
        :: "r"(smaddr), "l"(gptr) : "memory")
#define CP_COMMIT()  asm volatile("cp.async.commit_group;" ::: "memory")
#define CP_WAIT1()   asm volatile("cp.async.wait_group 1;" ::: "memory")
#define CP_WAIT0()   asm volatile("cp.async.wait_group 0;" ::: "memory")

static __device__ __forceinline__ uint32_t smem_u32(const void* p) {
    uint32_t a;
    asm("{ .reg .u64 t; cvta.to.shared.u64 t, %1; cvt.u32.u64 %0, t; }" : "=r"(a) : "l"(p));
    return a;
}

// ---- scratch (no allocations allowed) ----
__device__ float d_h  [NNODES * H];
__device__ float d_m  [NNODES * H];   // m, then reused for W2-pre
__device__ float d_agg[NNODES * H];
__device__ float d_v  [NNODES * H];
// bf16 hi/lo split operands (written directly by fused k3/k4)
__device__ __nv_bfloat16 d_ehi[(size_t)JPAD * KP];
__device__ __nv_bfloat16 d_elo[(size_t)JPAD * KP];
__device__ __nv_bfloat16 d_bhi[BATCH * BROWS * BSTRIDE];
__device__ __nv_bfloat16 d_blo[BATCH * BROWS * BSTRIDE];
__device__ __nv_bfloat16 d_shhi[BATCH * BSTRIDE];
__device__ __nv_bfloat16 d_shlo[BATCH * BSTRIDE];

// ------------------------------------------------------------------
// K1+P1 merged: blocks [0, P1BLKS) do embed hi/lo split;
// blocks [P1BLKS, P1BLKS+NNODES) do gather + GGC matmul + agg zero.
// ------------------------------------------------------------------
__global__ void k1p1(const int* __restrict__ x,
                     const float* __restrict__ embed,
                     const float* __restrict__ ggc)
{
    int t = threadIdx.x;
    if (blockIdx.x < P1BLKS) {
        int idx = blockIdx.x * 256 + t;
        int row = idx / KP, k = idx - row * KP;
        float val = (row < NNODE && k < H) ? embed[(size_t)row * H + k] : 0.f;
        __nv_bfloat16 hi = __float2bfloat16(val);
        d_ehi[idx] = hi;
        d_elo[idx] = __float2bfloat16(val - __bfloat162float(hi));
        return;
    }
    int i = blockIdx.x - P1BLKS;
    __shared__ float hs[H];
    int xi = x[i];
    if (t < H) {
        float val = embed[(size_t)xi * H + t];
        hs[t] = val;
        d_h[i * H + t] = val;
    }
    __syncthreads();
    if (t < H) {
        float acc = 0.f;
        #pragma unroll 4
        for (int k = 0; k < H; k++)
            acc = fmaf(hs[k], ggc[k * H + t], acc);
        d_m[i * H + t]   = acc;
        d_agg[i * H + t] = 0.f;
    }
}

// ------------------------------------------------------------------
// K2: agg[dst] += w_e * m[src]
// ------------------------------------------------------------------
__global__ void k2_scatter(const int* __restrict__ ei,
                           const float* __restrict__ ew)
{
    int idx = blockIdx.x * blockDim.x + threadIdx.x;
    if (idx >= EDGES * H) return;
    int e = idx / H;
    int h = idx - e * H;
    int src = ei[e];
    int dst = ei[EDGES + e];
    atomicAdd(&d_agg[dst * H + h], ew[e] * d_m[src * H + h]);
}

// ------------------------------------------------------------------
// K3: GRU + fused W2-pre + DIRECT bf16 hi/lo writes of vt/v B-rows.
// NPB=2 -> 512 CTAs. Node i -> b=i/16, l=i%16; vt row = b*32+l,
// v row = b*32+16+l; k in [100,120) zero-padded.
// ------------------------------------------------------------------
__global__ void __launch_bounds__(128)
k3_gru_post(const float* __restrict__ wih,
            const float* __restrict__ whh,
            const float* __restrict__ bih,
            const float* __restrict__ bhh,
            const float* __restrict__ W2,
            const float* __restrict__ b2,
            const float* __restrict__ Wt,
            const float* __restrict__ bt)
{
    int node0 = blockIdx.x * NPB;
    int c = threadIdx.x;
    __shared__ __align__(16) float ag[NPB * H];
    __shared__ __align__(16) float hh[NPB * H];
    __shared__ __align__(16) float vv[NPB * H];

    for (int idx = c; idx < NPB * H; idx += 128) {
        ag[idx] = d_agg[node0 * H + idx];
        hh[idx] = d_h  [node0 * H + idx];
    }
    __syncthreads();

    if (c < H) {
        float air[NPB], aiz[NPB], ain[NPB], ahr[NPB], ahz[NPB], ahn[NPB];
        float br = bih[c], bz = bih[H + c], bn = bih[2 * H + c];
        float cr = bhh[c], cz = bhh[H + c], cn = bhh[2 * H + c];
        #pragma unroll
        for (int n = 0; n < NPB; n++) {
            air[n] = br; aiz[n] = bz; ain[n] = bn;
            ahr[n] = cr; ahz[n] = cz; ahn[n] = cn;
        }
        const float4* wr4 = (const float4*)(wih + (size_t)c * H);
        const float4* wz4 = (const float4*)(wih + (size_t)(H + c) * H);
        const float4* wn4 = (const float4*)(wih + (size_t)(2 * H + c) * H);
        const float4* ur4 = (const float4*)(whh + (size_t)c * H);
        const float4* uz4 = (const float4*)(whh + (size_t)(H + c) * H);
        const float4* un4 = (const float4*)(whh + (size_t)(2 * H + c) * H);

        for (int k = 0; k < H4; k++) {
            float4 wr = wr4[k], wz = wz4[k], wn = wn4[k];
            float4 ur = ur4[k], uz = uz4[k], un = un4[k];
            #pragma unroll
            for (int n = 0; n < NPB; n++) {
                float4 a  = *(const float4*)&ag[n * H + 4 * k];
                float4 hv = *(const float4*)&hh[n * H + 4 * k];
                air[n] = fmaf(a.x, wr.x, air[n]); air[n] = fmaf(a.y, wr.y, air[n]);
                air[n] = fmaf(a.z, wr.z, air[n]); air[n] = fmaf(a.w, wr.w, air[n]);
                aiz[n] = fmaf(a.x, wz.x, aiz[n]); aiz[n] = fmaf(a.y, wz.y, aiz[n]);
                aiz[n] = fmaf(a.z, wz.z, aiz[n]); aiz[n] = fmaf(a.w, wz.w, aiz[n]);
                ain[n] = fmaf(a.x, wn.x, ain[n]); ain[n] = fmaf(a.y, wn.y, ain[n]);
                ain[n] = fmaf(a.z, wn.z, ain[n]); ain[n] = fmaf(a.w, wn.w, ain[n]);
                ahr[n] = fmaf(hv.x, ur.x, ahr[n]); ahr[n] = fmaf(hv.y, ur.y, ahr[n]);
                ahr[n] = fmaf(hv.z, ur.z, ahr[n]); ahr[n] = fmaf(hv.w, ur.w, ahr[n]);
                ahz[n] = fmaf(hv.x, uz.x, ahz[n]); ahz[n] = fmaf(hv.y, uz.y, ahz[n]);
                ahz[n] = fmaf(hv.z, uz.z, ahz[n]); ahz[n] = fmaf(hv.w, uz.w, ahz[n]);
                ahn[n] = fmaf(hv.x, un.x, ahn[n]); ahn[n] = fmaf(hv.y, un.y, ahn[n]);
                ahn[n] = fmaf(hv.z, un.z, ahn[n]); ahn[n] = fmaf(hv.w, un.w, ahn[n]);
            }
        }
        #pragma unroll
        for (int n = 0; n < NPB; n++) {
            float r  = 1.f / (1.f + __expf(-(air[n] + ahr[n])));
            float zg = 1.f / (1.f + __expf(-(aiz[n] + ahz[n])));
            float ng = tanhf(ain[n] + r * ahn[n]);
            float nv = (1.f - zg) * ng + zg * hh[n * H + c];
            vv[n * H + c] = nv;
            d_v[(node0 + n) * H + c] = nv;
        }
    }
    __syncthreads();

    // second phase: W2-pre (d_m) and vt -> direct bf16 split; v -> bf16 split
    #pragma unroll
    for (int n = 0; n < NPB; n++) {
        int node = node0 + n;
        int b = node >> 4, l = node & 15;
        int rowt = (b * 32 + l) * BSTRIDE;        // vt row
        int rowv = (b * 32 + 16 + l) * BSTRIDE;   // v row
        if (c < H) {
            float nv = vv[n * H + c];
            __nv_bfloat16 vhi = __float2bfloat16(nv);
            d_bhi[rowv + c] = vhi;
            d_blo[rowv + c] = __float2bfloat16(nv - __bfloat162float(vhi));
        } else if (c < BSTRIDE) {
            d_bhi[rowv + c] = __float2bfloat16(0.f);
            d_blo[rowv + c] = __float2bfloat16(0.f);
            d_bhi[rowt + c] = __float2bfloat16(0.f);
            d_blo[rowt + c] = __float2bfloat16(0.f);
        }
    }

    if (c < H) {
        float a2[NPB], a3[NPB];
        float bb2 = b2[c], bbt = bt[c];
        #pragma unroll
        for (int n = 0; n < NPB; n++) { a2[n] = bb2; a3[n] = bbt; }
        const float4* w2r = (const float4*)(W2 + (size_t)c * H);
        const float4* wtr = (const float4*)(Wt + (size_t)c * H);
        for (int k = 0; k < H4; k++) {
            float4 w2 = w2r[k], wt = wtr[k];
            #pragma unroll
            for (int n = 0; n < NPB; n++) {
                float4 v = *(const float4*)&vv[n * H + 4 * k];
                a2[n] = fmaf(v.x, w2.x, a2[n]); a2[n] = fmaf(v.y, w2.y, a2[n]);
                a2[n] = fmaf(v.z, w2.z, a2[n]); a2[n] = fmaf(v.w, w2.w, a2[n]);
                a3[n] = fmaf(v.x, wt.x, a3[n]); a3[n] = fmaf(v.y, wt.y, a3[n]);
                a3[n] = fmaf(v.z, wt.z, a3[n]); a3[n] = fmaf(v.w, wt.w, a3[n]);
            }
        }
        #pragma unroll
        for (int n = 0; n < NPB; n++) {
            int node = node0 + n;
            int b = node >> 4, l = node & 15;
            int rowt = (b * 32 + l) * BSTRIDE;
            d_m[node * H + c] = a2[n];                // W2-pre for k4
            __nv_bfloat16 thi = __float2bfloat16(a3[n]);
            d_bhi[rowt + c] = thi;
            d_blo[rowt + c] = __float2bfloat16(a3[n] - __bfloat162float(thi));
        }
    }
}

// ------------------------------------------------------------------
// K4: per-batch reductions -> s_h, written directly as bf16 hi/lo.
// alpha parallelized over 16 l x 8 lanes.
// ------------------------------------------------------------------
__global__ void k4_attn(const float* __restrict__ W1, const float* __restrict__ b1,
                        const float* __restrict__ qw, const float* __restrict__ qb,
                        const float* __restrict__ W3, const float* __restrict__ b3)
{
    int b = blockIdx.x;
    int t = threadIdx.x;
    __shared__ __align__(16) float sl[H];
    __shared__ float w1s[H];
    __shared__ float as[LSEQ * H];
    __shared__ float alpha[LSEQ];
    __shared__ __align__(16) float sg[H];

    if (t < H) sl[t] = d_v[(b * LSEQ + LSEQ - 1) * H + t];
    __syncthreads();

    if (t < H) {
        float acc = b1[t];
        const float4* w = (const float4*)(W1 + (size_t)t * H);
        for (int k = 0; k < H4; k++) {
            float4 wv = w[k];
            float4 s = *(const float4*)&sl[4 * k];
            acc = fmaf(s.x, wv.x, acc); acc = fmaf(s.y, wv.y, acc);
            acc = fmaf(s.z, wv.z, acc); acc = fmaf(s.w, wv.w, acc);
        }
        w1s[t] = acc;
    }
    __syncthreads();

    for (int idx = t; idx < LSEQ * H; idx += blockDim.x) {
        int l = idx / H, hh2 = idx - l * H;
        float pre = d_m[(b * LSEQ + l) * H + hh2];
        as[idx] = 1.f / (1.f + __expf(-(w1s[hh2] + pre)));
    }
    __syncthreads();

    {   // alpha[l] = as[l,:] . qw + qb   (16 l x 8 lanes)
        int l = t >> 3, s = t & 7;
        float acc = 0.f;
        for (int k = s; k < H; k += 8) acc = fmaf(as[l * H + k], qw[k], acc);
        acc += __shfl_xor_sync(0xffffffffu, acc, 1);
        acc += __shfl_xor_sync(0xffffffffu, acc, 2);
        acc += __shfl_xor_sync(0xffffffffu, acc, 4);
        if (s == 0) alpha[l] = acc + qb[0];
    }
    __syncthreads();

    if (t < H) {
        float acc = 0.f;
        for (int l = 0; l < LSEQ; l++) acc = fmaf(alpha[l], d_v[(b * LSEQ + l) * H + t], acc);
        sg[t] = acc;
    }
    __syncthreads();

    if (t < H) {
        float acc = b3[t];
        const float4* w  = (const float4*)(W3 + (size_t)t * 2 * H);
        for (int k = 0; k < H4; k++) {
            float4 wv = w[k];
            float4 s = *(const float4*)&sl[4 * k];
            acc = fmaf(s.x, wv.x, acc); acc = fmaf(s.y, wv.y, acc);
            acc = fmaf(s.z, wv.z, acc); acc = fmaf(s.w, wv.w, acc);
        }
        for (int k = 0; k < H4; k++) {
            float4 wv = w[H4 + k];
            float4 s = *(const float4*)&sg[4 * k];
            acc = fmaf(s.x, wv.x, acc); acc = fmaf(s.y, wv.y, acc);
            acc = fmaf(s.z, wv.z, acc); acc = fmaf(s.w, wv.w, acc);
        }
        __nv_bfloat16 hi = __float2bfloat16(acc);
        d_shhi[b * BSTRIDE + t] = hi;
        d_shlo[b * BSTRIDE + t] = __float2bfloat16(acc - __bfloat162float(hi));
    } else if (t < BSTRIDE) {
        d_shhi[b * BSTRIDE + t] = __float2bfloat16(0.f);
        d_shlo[b * BSTRIDE + t] = __float2bfloat16(0.f);
    }
}

// ------------------------------------------------------------------
// K5: HMMA GEMM + softmax epilogue, batch-split grid (313, 8).
// (unchanged from R12)
// ------------------------------------------------------------------
#define SM_BBUF  0
#define BUFB     15360
#define SM_ALO   46080
#define SM_BASE  76800
#define SMEM_K5  81408
#define BASE_STRIDE 9
#define BQ1      (BROWS * BSTRIDE)   // 3840 bf16 per split per batch

__global__ void __launch_bounds__(256, 2)
k5_hmma(float* __restrict__ out)
{
    extern __shared__ __align__(16) char dsm[];
    uint32_t smb = smem_u32(dsm);
    float* s_base = (float*)(dsm + SM_BASE);

    int tid  = threadIdx.x;
    int wid  = tid >> 5;
    int lane = tid & 31;
    int grp  = lane >> 2;
    int qid  = lane & 3;
    int tile = blockIdx.x;
    int b0   = blockIdx.y * BCH;

    // ---- A-hi fragments, register-resident ----
    uint32_t ahi[KSTEPS][4];
    {
        int r0 = tile * MT + wid * 16 + grp;
        int r1 = r0 + 8;
        #pragma unroll
        for (int ks = 0; ks < KSTEPS; ks++) {
            int k0 = ks * 16 + 2 * qid;
            ahi[ks][0] = *(const uint32_t*)(d_ehi + (size_t)r0 * KP + k0);
            ahi[ks][1] = *(const uint32_t*)(d_ehi + (size_t)r1 * KP + k0);
            ahi[ks][2] = *(const uint32_t*)(d_ehi + (size_t)r0 * KP + k0 + 8);
            ahi[ks][3] = *(const uint32_t*)(d_ehi + (size_t)r1 * KP + k0 + 8);
        }
    }

    // ---- stage A-lo tile (128 x 112 bf16, stride 120) + sh rows ----
    {
        const __nv_bfloat16* src = d_elo + (size_t)tile * MT * KP;
        for (int c = tid; c < MT * 14; c += 256) {
            int row = c / 14, cc = c - row * 14;
            uint32_t dst = smb + SM_ALO + row * 240 + cc * 16;
            CP_ASYNC16(dst, (const char*)(src + (size_t)row * KP) + cc * 16);
        }
        for (int c = tid; c < 120; c += 256) {
            uint32_t dst = smb + SM_BBUF + c * 16;
            CP_ASYNC16(dst, (const char*)(d_shhi + (size_t)b0 * BSTRIDE) + c * 16);
            CP_ASYNC16(dst + 7680, (const char*)(d_shlo + (size_t)b0 * BSTRIDE) + c * 16);
        }
        CP_COMMIT();
        CP_WAIT0();
    }
    __syncthreads();

    uint32_t alo_addr = smb + SM_ALO + (wid * 16 + (lane & 15)) * 240
                        + ((lane >> 4) * 8) * 2;
    uint32_t brow_off = lane * 240;

    int rl0 = wid * 16 + grp;

    // ===== PHASE 0: base GEMM for this chunk's 8 columns =====
    {
        const __nv_bfloat16* Bh = (const __nv_bfloat16*)(dsm + SM_BBUF);
        const __nv_bfloat16* Bl = (const __nv_bfloat16*)(dsm + SM_BBUF + 7680);
        float Db[4] = {0.f, 0.f, 0.f, 0.f};
        #pragma unroll
        for (int ks = 0; ks < KSTEPS; ks++) {
            int kb = ks * 16 + 2 * qid;
            uint32_t al[4];
            LDSM4(al[0], al[1], al[2], al[3], alo_addr + ks * 32);
            int n = grp;
            uint32_t bh0 = *(const uint32_t*)(Bh + n * BSTRIDE + kb);
            uint32_t bh1 = *(const uint32_t*)(Bh + n * BSTRIDE + kb + 8);
            uint32_t bl0 = *(const uint32_t*)(Bl + n * BSTRIDE + kb);
            uint32_t bl1 = *(const uint32_t*)(Bl + n * BSTRIDE + kb + 8);
            MMA16816(Db, ahi[ks], bh0, bh1);
            MMA16816(Db, ahi[ks], bl0, bl1);
            MMA16816(Db, al,      bh0, bh1);
        }
        int c0 = 2 * qid;
        s_base[rl0 * BASE_STRIDE + c0]           = Db[0];
        s_base[rl0 * BASE_STRIDE + c0 + 1]       = Db[1];
        s_base[(rl0 + 8) * BASE_STRIDE + c0]     = Db[2];
        s_base[(rl0 + 8) * BASE_STRIDE + c0 + 1] = Db[3];
        __syncthreads();
    }

    // ---- prime cp.async pipeline: local batches 0 and 1 ----
    #pragma unroll
    for (int pb = 0; pb < 2; pb++) {
        uint32_t dst = smb + SM_BBUF + pb * BUFB;
        const char* sh = (const char*)(d_bhi + (size_t)(b0 + pb) * BQ1);
        const char* sl = (const char*)(d_blo + (size_t)(b0 + pb) * BQ1);
        for (int c = tid; c < 480; c += 256) {
            CP_ASYNC16(dst + c * 16, sh + c * 16);
            CP_ASYNC16(dst + 7680 + c * 16, sl + c * 16);
        }
        CP_COMMIT();
    }
    CP_WAIT1();
    __syncthreads();

    int j0 = tile * MT + rl0;
    int j1 = j0 + 8;

    #pragma unroll 1
    for (int b = 0; b < BCH; b++) {
        int bg = b0 + b;
        uint32_t bufb = smb + SM_BBUF + (b % 3) * BUFB;

        // ---- MMA mainloop ----
        float D[NTL][4];
        #pragma unroll
        for (int nt = 0; nt < NTL; nt++)
            { D[nt][0] = 0.f; D[nt][1] = 0.f; D[nt][2] = 0.f; D[nt][3] = 0.f; }

        #pragma unroll
        for (int ks = 0; ks < KSTEPS; ks++) {
            uint32_t al[4], bh0[4], bh1[4], bl0[4], bl1[4];
            LDSM4(al[0], al[1], al[2], al[3], alo_addr + ks * 32);
            LDSM4(bh0[0], bh0[1], bh0[2], bh0[3], bufb + brow_off + ks * 32);
            LDSM4(bh1[0], bh1[1], bh1[2], bh1[3], bufb + brow_off + ks * 32 + 16);
            LDSM4(bl0[0], bl0[1], bl0[2], bl0[3], bufb + 7680 + brow_off + ks * 32);
            LDSM4(bl1[0], bl1[1], bl1[2], bl1[3], bufb + 7680 + brow_off + ks * 32 + 16);
            #pragma unroll
            for (int nt = 0; nt < NTL; nt++) MMA16816(D[nt], ahi[ks], bh0[nt], bh1[nt]);
            #pragma unroll
            for (int nt = 0; nt < NTL; nt++) MMA16816(D[nt], ahi[ks], bl0[nt], bl1[nt]);
            #pragma unroll
            for (int nt = 0; nt < NTL; nt++) MMA16816(D[nt], al,      bh0[nt], bh1[nt]);
        }

        // ---- prefetch local batch b+2 (always commit a group) ----
        if (b + 2 < BCH) {
            uint32_t dst = smb + SM_BBUF + ((b + 2) % 3) * BUFB;
            const char* sh = (const char*)(d_bhi + (size_t)(bg + 2) * BQ1);
            const char* sl = (const char*)(d_blo + (size_t)(bg + 2) * BQ1);
            for (int c = tid; c < 480; c += 256) {
                CP_ASYNC16(dst + c * 16, sh + c * 16);
                CP_ASYNC16(dst + 7680 + c * 16, sl + c * 16);
            }
        }
        CP_COMMIT();

        // ---- epilogue (no-max softmax; logits are O(1) here) ----
        {
            float base0 = s_base[rl0 * BASE_STRIDE + b];
            float base1 = s_base[(rl0 + 8) * BASE_STRIDE + b];

            float e00 = __expf(D[0][0]), e01 = __expf(D[0][1]);
            float e10 = __expf(D[1][0]), e11 = __expf(D[1][1]);
            float es0 = (e00 + e01) + (e10 + e11);
            float ws0 = fmaf(e00, D[2][0], fmaf(e01, D[2][1],
                        fmaf(e10, D[3][0], e11 * D[3][1])));

            float f00 = __expf(D[0][2]), f01 = __expf(D[0][3]);
            float f10 = __expf(D[1][2]), f11 = __expf(D[1][3]);
            float es1 = (f00 + f01) + (f10 + f11);
            float ws1 = fmaf(f00, D[2][2], fmaf(f01, D[2][3],
                        fmaf(f10, D[3][2], f11 * D[3][3])));

            es0 += __shfl_xor_sync(0xffffffffu, es0, 1);
            ws0 += __shfl_xor_sync(0xffffffffu, ws0, 1);
            es1 += __shfl_xor_sync(0xffffffffu, es1, 1);
            ws1 += __shfl_xor_sync(0xffffffffu, ws1, 1);
            es0 += __shfl_xor_sync(0xffffffffu, es0, 2);
            ws0 += __shfl_xor_sync(0xffffffffu, ws0, 2);
            es1 += __shfl_xor_sync(0xffffffffu, es1, 2);
            ws1 += __shfl_xor_sync(0xffffffffu, ws1, 2);

            if (qid == 0) {
                if (j0 < NNODE) out[(size_t)bg * NNODE + j0] = base0 + ws0 / es0;
                if (j1 < NNODE) out[(size_t)bg * NNODE + j1] = base1 + ws1 / es1;
            }
        }

        CP_WAIT1();
        __syncthreads();
    }
}

// ------------------------------------------------------------------
extern "C" void kernel_launch(void* const* d_in, const int* in_sizes, int n_in,
                              void* d_out, int out_size)
{
    const int*   x     = (const int*)  d_in[0];
    const int*   ei    = (const int*)  d_in[1];
    const float* ew    = (const float*)d_in[2];
    // d_in[3] = batch (unused)
    const float* embed = (const float*)d_in[4];
    const float* ggc   = (const float*)d_in[5];
    const float* wih   = (const float*)d_in[6];
    const float* whh   = (const float*)d_in[7];
    const float* bih   = (const float*)d_in[8];
    const float* bhh   = (const float*)d_in[9];
    const float* W1    = (const float*)d_in[10];
    const float* b1    = (const float*)d_in[11];
    const float* W2    = (const float*)d_in[12];
    const float* b2    = (const float*)d_in[13];
    const float* Wt    = (const float*)d_in[14];
    const float* bt    = (const float*)d_in[15];
    const float* qw    = (const float*)d_in[16];
    const float* qb    = (const float*)d_in[17];
    const float* W3    = (const float*)d_in[18];
    const float* b3    = (const float*)d_in[19];
    float* out = (float*)d_out;

    cudaFuncSetAttribute(k5_hmma, cudaFuncAttributeMaxDynamicSharedMemorySize, SMEM_K5);

    k1p1       <<<P1BLKS + NNODES, 256>>>(x, embed, ggc);
    k2_scatter <<<(EDGES * H + 255) / 256, 256>>>(ei, ew);
    k3_gru_post<<<NNODES / NPB, 128>>>(wih, whh, bih, bhh, W2, b2, Wt, bt);
    k4_attn    <<<BATCH, 128>>>(W1, b1, qw, qb, W3, b3);
    dim3 g5(NTILES, NBY);
    k5_hmma    <<<g5, 256, SMEM_K5>>>(out);
}